// round 1
// baseline (speedup 1.0000x reference)
#include <cuda_runtime.h>
#include <cuda_bf16.h>

// Problem: elementwise theta-step + scalar residual-norm reduction.
// x: (4096, 16384) fp32 -> out: same shape, plus fmin scalar appended.

#define NBLOCKS   3552      // 148 SMs * 24 blocks
#define NTHREADS  256

__device__ float g_partials[NBLOCKS];

__device__ __forceinline__ float proc_one(float x, float& r2acc) {
    // explicit = x + 0.5*relu(x)
    float e = fmaf(0.5f, fmaxf(x, 0.0f), x);
    float z = e;
    #pragma unroll
    for (int k = 0; k < 10; ++k) {
        z = fmaf(0.5f, fmaxf(z, 0.0f), e);
    }
    float rz = fmaxf(z, 0.0f);
    float o  = fmaf(0.5f, rz, e);
    // residual exactly in reference order: (z - explicit) - 0.5*relu(z)
    float r  = (z - e) - 0.5f * rz;
    r2acc = fmaf(r, r, r2acc);
    return o;
}

__global__ void __launch_bounds__(NTHREADS)
step_kernel(const float4* __restrict__ x4, float4* __restrict__ out4, int n4) {
    int tid    = blockIdx.x * NTHREADS + threadIdx.x;
    int stride = gridDim.x * NTHREADS;

    float local = 0.0f;
    for (int i = tid; i < n4; i += stride) {
        float4 v = __ldg(&x4[i]);
        float4 o;
        o.x = proc_one(v.x, local);
        o.y = proc_one(v.y, local);
        o.z = proc_one(v.z, local);
        o.w = proc_one(v.w, local);
        out4[i] = o;
    }

    // block reduction of r^2 partial
    #pragma unroll
    for (int off = 16; off > 0; off >>= 1)
        local += __shfl_down_sync(0xffffffffu, local, off);

    __shared__ float warpsum[NTHREADS / 32];
    int lane = threadIdx.x & 31;
    int wid  = threadIdx.x >> 5;
    if (lane == 0) warpsum[wid] = local;
    __syncthreads();

    if (wid == 0) {
        float v = (lane < NTHREADS / 32) ? warpsum[lane] : 0.0f;
        #pragma unroll
        for (int off = 4; off > 0; off >>= 1)
            v += __shfl_down_sync(0xffffffffu, v, off);
        if (lane == 0) g_partials[blockIdx.x] = v;
    }
}

__global__ void __launch_bounds__(1024)
reduce_kernel(float* __restrict__ out_scalar) {
    // sum NBLOCKS partials in double, write 0.5 * sum
    double acc = 0.0;
    for (int i = threadIdx.x; i < NBLOCKS; i += 1024)
        acc += (double)g_partials[i];

    #pragma unroll
    for (int off = 16; off > 0; off >>= 1)
        acc += __shfl_down_sync(0xffffffffu, acc, off);

    __shared__ double warpsum[32];
    int lane = threadIdx.x & 31;
    int wid  = threadIdx.x >> 5;
    if (lane == 0) warpsum[wid] = acc;
    __syncthreads();

    if (wid == 0) {
        double v = (lane < 32) ? warpsum[lane] : 0.0;
        #pragma unroll
        for (int off = 16; off > 0; off >>= 1)
            v += __shfl_down_sync(0xffffffffu, v, off);
        if (lane == 0) out_scalar[0] = (float)(0.5 * v);
    }
}

extern "C" void kernel_launch(void* const* d_in, const int* in_sizes, int n_in,
                              void* d_out, int out_size) {
    const float* x = (const float*)d_in[0];
    float* out     = (float*)d_out;
    int n  = in_sizes[0];          // 67108864, divisible by 4
    int n4 = n >> 2;

    step_kernel<<<NBLOCKS, NTHREADS>>>((const float4*)x, (float4*)out, n4);
    reduce_kernel<<<1, 1024>>>(out + n);
}